// round 5
// baseline (speedup 1.0000x reference)
#include <cuda_runtime.h>
#include <cstdint>

// FWHT over contiguous groups of 128 fp32 elements.
// 16 lanes per group; each thread holds 8 CONTIGUOUS elements (one 32B v8
// load, sm_100+ 256-bit LDG/STG). Stages h=1,2,4 intra-thread; stages
// h=8,16,32,64 via shfl.xor deltas 1,2,4,8 (stay within 16-lane halves).
// 2 groups per thread (lanes 0-15 -> group 2p, lanes 16-31 -> group 2p+1,
// p=0,1) -> 2 front-batched LDG.256 per thread.

#define NPG 2  // group-slots per thread

__device__ __forceinline__ void ldg256(const float* p, float* r) {
    asm volatile(
        "ld.global.cs.v8.f32 {%0,%1,%2,%3,%4,%5,%6,%7}, [%8];"
        : "=f"(r[0]), "=f"(r[1]), "=f"(r[2]), "=f"(r[3]),
          "=f"(r[4]), "=f"(r[5]), "=f"(r[6]), "=f"(r[7])
        : "l"(p));
}

__device__ __forceinline__ void stg256(float* p, const float* r) {
    asm volatile(
        "st.global.cs.v8.f32 [%0], {%1,%2,%3,%4,%5,%6,%7,%8};"
        :: "l"(p),
           "f"(r[0]), "f"(r[1]), "f"(r[2]), "f"(r[3]),
           "f"(r[4]), "f"(r[5]), "f"(r[6]), "f"(r[7])
        : "memory");
}

__global__ void __launch_bounds__(256, 8) fwht128_kernel(
    const float* __restrict__ in, float* __restrict__ out)
{
    const unsigned int lane = threadIdx.x & 31u;
    const unsigned int l16  = lane & 15u;
    const unsigned int half = lane >> 4;         // which group of the pair
    const unsigned int wid  = threadIdx.x >> 5;
    // each warp owns NPG*2 = 4 consecutive groups = 512 floats
    const unsigned int wbase = (blockIdx.x * 8u + wid) * (NPG * 256u);
    // per-thread element base within slot p: wbase + p*256 + half*128 + 8*l16
    const unsigned int tbase = wbase + half * 128u + 8u * l16;

    // Front-batched 256-bit loads.
    float x[NPG][8];
    #pragma unroll
    for (int p = 0; p < NPG; ++p)
        ldg256(in + tbase + (unsigned)p * 256u, x[p]);

    // Intra-thread stages h=1,2,4 on 8 contiguous elements.
    #pragma unroll
    for (int p = 0; p < NPG; ++p) {
        float* e = x[p];
        // h=1
        float t;
        t = e[0]; e[0] = t + e[1]; e[1] = t - e[1];
        t = e[2]; e[2] = t + e[3]; e[3] = t - e[3];
        t = e[4]; e[4] = t + e[5]; e[5] = t - e[5];
        t = e[6]; e[6] = t + e[7]; e[7] = t - e[7];
        // h=2
        t = e[0]; e[0] = t + e[2]; e[2] = t - e[2];
        t = e[1]; e[1] = t + e[3]; e[3] = t - e[3];
        t = e[4]; e[4] = t + e[6]; e[6] = t - e[6];
        t = e[5]; e[5] = t + e[7]; e[7] = t - e[7];
        // h=4
        t = e[0]; e[0] = t + e[4]; e[4] = t - e[4];
        t = e[1]; e[1] = t + e[5]; e[5] = t - e[5];
        t = e[2]; e[2] = t + e[6]; e[6] = t - e[6];
        t = e[3]; e[3] = t + e[7]; e[7] = t - e[7];
    }

    // Cross-lane stages h=8,16,32,64 -> shfl.xor deltas 1,2,4,8.
    #pragma unroll
    for (int d = 1; d <= 8; d <<= 1) {
        bool up = (lane & (unsigned)d) != 0u;
        #pragma unroll
        for (int p = 0; p < NPG; ++p) {
            #pragma unroll
            for (int k = 0; k < 8; ++k) {
                float q = __shfl_xor_sync(0xffffffffu, x[p][k], d);
                x[p][k] = up ? (q - x[p][k]) : (x[p][k] + q);
            }
        }
    }

    const float S = 0.08838834764831845f;  // 1/sqrt(128)
    #pragma unroll
    for (int p = 0; p < NPG; ++p) {
        float r[8];
        #pragma unroll
        for (int k = 0; k < 8; ++k) r[k] = x[p][k] * S;
        stg256(out + tbase + (unsigned)p * 256u, r);
    }
}

extern "C" void kernel_launch(void* const* d_in, const int* in_sizes, int n_in,
                              void* d_out, int out_size)
{
    const float* x = (const float*)d_in[0];
    float* y = (float*)d_out;
    // 67108864 floats; each block consumes 8 warps * 512 = 4096 floats.
    unsigned int n = (unsigned int)in_sizes[0];
    unsigned int grid = n / 4096u;  // = 16384
    fwht128_kernel<<<grid, 256>>>(x, y);
}